// round 7
// baseline (speedup 1.0000x reference)
#include <cuda_runtime.h>
#include <cuda_bf16.h>
#include <math.h>

#define IN_C  128
#define HID_C 64
#define OUT_C 32
#define NMAX  100096   // padded headroom, n = 100000
#define EMAX  1600512

// ---------------- scratch (device globals; no allocation allowed) ----------
__device__ int   g_is64;                  // 1 if edge_index is int64
__device__ __align__(16) int   g_src [EMAX];
__device__ __align__(16) int   g_dst [EMAX];
__device__ __align__(16) float g_dinv [NMAX];
__device__ __align__(16) float g_h1pre[NMAX * HID_C];
__device__ __align__(16) float g_agg1 [NMAX * HID_C];   // becomes h1 after finalize1
__device__ __align__(16) float g_h2pre[NMAX * OUT_C];
__device__ __align__(16) float g_agg2 [NMAX * OUT_C];   // becomes h2 after finalize2

// ---------------- dtype detect + index conversion ---------------------------
__global__ void detect_kernel(const void* ei, int n) {
    // single thread: safe to read first 64 int64 slots in either layout
    const long long* p = (const long long*)ei;
    int ok = 1;
    for (int i = 0; i < 64; i++) {
        long long v = p[i];
        if (v < 0 || v >= (long long)n) { ok = 0; break; }
    }
    g_is64 = ok;
}

__global__ void convert_kernel(const void* ei, int E, int n) {
    int i = blockIdx.x * blockDim.x + threadIdx.x;
    if (i >= E) return;
    int s, d;
    if (g_is64) {
        const long long* p = (const long long*)ei;
        s = (int)p[i];
        d = (int)p[E + i];
    } else {
        const int* p = (const int*)ei;
        s = p[i];
        d = p[E + i];
    }
    // clamp defensively: any out-of-range index becomes node 0 rather than UB
    g_src[i] = (unsigned)s < (unsigned)n ? s : 0;
    g_dst[i] = (unsigned)d < (unsigned)n ? d : 0;
}

// ---------------- zero ------------------------------------------------------
__global__ void zero4_kernel(float4* p, int n4) {
    int i = blockIdx.x * blockDim.x + threadIdx.x;
    if (i < n4) p[i] = make_float4(0.f, 0.f, 0.f, 0.f);
}

// ---------------- degree / dinv --------------------------------------------
__global__ void deg_kernel(int E) {
    int e = blockIdx.x * blockDim.x + threadIdx.x;
    if (e < E) atomicAdd(&g_dinv[g_dst[e]], 1.0f);
}
__global__ void dinv_kernel(int n) {
    int i = blockIdx.x * blockDim.x + threadIdx.x;
    if (i < n) g_dinv[i] = rsqrtf(g_dinv[i] + 1.0f);
}

// ---------------- tiled SGEMM: C[M,BN] = A[M,K] @ B[K,BN] -------------------
template <int BM, int BN, int BK, int TM, int TN, int K>
__global__ void sgemm_kernel(const float* __restrict__ A,
                             const float* __restrict__ B,
                             float* __restrict__ C, int M) {
    constexpr int THREADS = (BM / TM) * (BN / TN);
    __shared__ float As[BK][BM];
    __shared__ float Bs[BK][BN];

    const int tid = threadIdx.x;
    const int tx = tid % (BN / TN);
    const int ty = tid / (BN / TN);
    const int rowBase = blockIdx.x * BM;

    float acc[TM][TN];
#pragma unroll
    for (int i = 0; i < TM; i++)
#pragma unroll
        for (int j = 0; j < TN; j++) acc[i][j] = 0.f;

    for (int kt = 0; kt < K; kt += BK) {
        constexpr int A_LD4 = BM * BK / 4;
#pragma unroll
        for (int i = tid; i < A_LD4; i += THREADS) {
            int idx = i * 4;
            int r = idx / BK;
            int c = idx % BK;
            int grow = rowBase + r;
            float4 v = (grow < M) ? *(const float4*)(A + (size_t)grow * K + kt + c)
                                  : make_float4(0.f, 0.f, 0.f, 0.f);
            As[c + 0][r] = v.x; As[c + 1][r] = v.y;
            As[c + 2][r] = v.z; As[c + 3][r] = v.w;
        }
        constexpr int B_LD4 = BK * BN / 4;
#pragma unroll
        for (int i = tid; i < B_LD4; i += THREADS) {
            int idx = i * 4;
            int r = idx / BN;
            int c = idx % BN;
            *(float4*)(&Bs[r][c]) = *(const float4*)(B + (size_t)(kt + r) * BN + c);
        }
        __syncthreads();

#pragma unroll
        for (int k = 0; k < BK; k++) {
            float ra[TM], rb[TN];
#pragma unroll
            for (int i = 0; i < TM; i++) ra[i] = As[k][ty * TM + i];
#pragma unroll
            for (int j = 0; j < TN; j++) rb[j] = Bs[k][tx * TN + j];
#pragma unroll
            for (int i = 0; i < TM; i++)
#pragma unroll
                for (int j = 0; j < TN; j++) acc[i][j] += ra[i] * rb[j];
        }
        __syncthreads();
    }

#pragma unroll
    for (int i = 0; i < TM; i++) {
        int grow = rowBase + ty * TM + i;
        if (grow < M) {
#pragma unroll
            for (int j = 0; j < TN; j++)
                C[(size_t)grow * BN + tx * TN + j] = acc[i][j];
        }
    }
}

// ---------------- edge scatter: agg[dst] += h[src] * dinv[s]*dinv[d] --------
template <int C>
__global__ void scatter_kernel(int E,
                               const float* __restrict__ h,
                               float* __restrict__ agg) {
    constexpr int CH = C / 4;           // float4 chunks per row (16 or 8)
    int t = blockIdx.x * blockDim.x + threadIdx.x;
    int e = t / CH;
    if (e >= E) return;
    int c = t - e * CH;
    int s = g_src[e];
    int d = g_dst[e];
    float norm = g_dinv[s] * g_dinv[d];
    float4 v = *(const float4*)(h + (size_t)s * C + 4 * c);
    float* p = agg + (size_t)d * C + 4 * c;
    atomicAdd(p + 0, v.x * norm);
    atomicAdd(p + 1, v.y * norm);
    atomicAdd(p + 2, v.z * norm);
    atomicAdd(p + 3, v.w * norm);
}

// ---------------- finalize: agg += hpre*dinv^2 + b (layer1 with relu) -------
__global__ void finalize1_kernel(const float* __restrict__ b1, int n) {
    int i = blockIdx.x * blockDim.x + threadIdx.x;   // over n * (HID_C/4)
    if (i >= n * (HID_C / 4)) return;
    int node = i >> 4;                 // HID_C/4 = 16
    int c4 = i & 15;
    float di = g_dinv[node];
    float d2 = di * di;
    float4 a = ((float4*)g_agg1)[i];
    float4 h = ((const float4*)g_h1pre)[i];
    float4 b = ((const float4*)b1)[c4];
    a.x = fmaxf(a.x + h.x * d2 + b.x, 0.f);
    a.y = fmaxf(a.y + h.y * d2 + b.y, 0.f);
    a.z = fmaxf(a.z + h.z * d2 + b.z, 0.f);
    a.w = fmaxf(a.w + h.w * d2 + b.w, 0.f);
    ((float4*)g_agg1)[i] = a;
}

__global__ void finalize2_kernel(const float* __restrict__ b2, int n) {
    int i = blockIdx.x * blockDim.x + threadIdx.x;   // over n * (OUT_C/4)
    if (i >= n * (OUT_C / 4)) return;
    int node = i >> 3;                 // OUT_C/4 = 8
    int c4 = i & 7;
    float di = g_dinv[node];
    float d2 = di * di;
    float4 a = ((float4*)g_agg2)[i];
    float4 h = ((const float4*)g_h2pre)[i];
    float4 b = ((const float4*)b2)[c4];
    a.x = a.x + h.x * d2 + b.x;
    a.y = a.y + h.y * d2 + b.y;
    a.z = a.z + h.z * d2 + b.z;
    a.w = a.w + h.w * d2 + b.w;
    ((float4*)g_agg2)[i] = a;
}

// ---------------- fused final layer: [x,h1,h2] @ Wl + bl -> log_softmax -----
// warp processes 4 rows; 7 feature segments of 32; Wl (224x32) in smem.
__global__ void final_kernel(const float* __restrict__ x,
                             const float* __restrict__ Wl,
                             const float* __restrict__ bl,
                             float* __restrict__ out, int n) {
    constexpr int KTOT = IN_C + HID_C + OUT_C;   // 224
    __shared__ float Ws[KTOT * OUT_C];           // 28 KB
    const int tid = threadIdx.x;
    for (int i = tid; i < KTOT * OUT_C / 4; i += blockDim.x)
        ((float4*)Ws)[i] = ((const float4*)Wl)[i];
    __syncthreads();

    const int warp = tid >> 5;
    const int lane = tid & 31;
    const int rowBase = (blockIdx.x * 8 + warp) * 4;
    if (rowBase >= n) return;

    float fr[4][7];
#pragma unroll
    for (int r = 0; r < 4; r++) {
        int row = rowBase + r;
        if (row < n) {
#pragma unroll
            for (int i = 0; i < 4; i++)
                fr[r][i] = x[(size_t)row * IN_C + i * 32 + lane];
            fr[r][4] = g_agg1[(size_t)row * HID_C + lane];
            fr[r][5] = g_agg1[(size_t)row * HID_C + 32 + lane];
            fr[r][6] = g_agg2[(size_t)row * OUT_C + lane];
        } else {
#pragma unroll
            for (int i = 0; i < 7; i++) fr[r][i] = 0.f;
        }
    }

    float acc[4] = {0.f, 0.f, 0.f, 0.f};
#pragma unroll
    for (int seg = 0; seg < 7; seg++) {
#pragma unroll
        for (int kk = 0; kk < 32; kk++) {
            float w = Ws[(seg * 32 + kk) * OUT_C + lane];
            acc[0] += __shfl_sync(0xffffffffu, fr[0][seg], kk) * w;
            acc[1] += __shfl_sync(0xffffffffu, fr[1][seg], kk) * w;
            acc[2] += __shfl_sync(0xffffffffu, fr[2][seg], kk) * w;
            acc[3] += __shfl_sync(0xffffffffu, fr[3][seg], kk) * w;
        }
    }

    float blv = bl[lane];
#pragma unroll
    for (int r = 0; r < 4; r++) {
        int row = rowBase + r;
        if (row >= n) break;           // uniform across warp
        float lg = acc[r] + blv;
        float m = lg;
#pragma unroll
        for (int o = 16; o > 0; o >>= 1)
            m = fmaxf(m, __shfl_xor_sync(0xffffffffu, m, o));
        float ex = __expf(lg - m);
        float s = ex;
#pragma unroll
        for (int o = 16; o > 0; o >>= 1)
            s += __shfl_xor_sync(0xffffffffu, s, o);
        out[(size_t)row * OUT_C + lane] = lg - m - __logf(s);
    }
}

// ---------------- launch ----------------------------------------------------
extern "C" void kernel_launch(void* const* d_in, const int* in_sizes, int n_in,
                              void* d_out, int out_size) {
    const float* x  = (const float*)d_in[0];
    const void*  ei = d_in[1];
    const float* W1 = (const float*)d_in[2];
    const float* b1 = (const float*)d_in[3];
    const float* W2 = (const float*)d_in[4];
    const float* b2 = (const float*)d_in[5];
    const float* Wl = (const float*)d_in[6];
    const float* bl = (const float*)d_in[7];
    float* out = (float*)d_out;

    const int n = in_sizes[0] / IN_C;
    const int E = in_sizes[1] / 2;

    float *dinv, *agg1, *agg2, *h1pre, *h2pre;
    cudaGetSymbolAddress((void**)&dinv,  g_dinv);
    cudaGetSymbolAddress((void**)&h1pre, g_h1pre);
    cudaGetSymbolAddress((void**)&agg1,  g_agg1);
    cudaGetSymbolAddress((void**)&h2pre, g_h2pre);
    cudaGetSymbolAddress((void**)&agg2,  g_agg2);

    const int T = 256;

    // edge dtype detect + convert to int32 arrays
    detect_kernel<<<1, 1>>>(ei, n);
    convert_kernel<<<(E + T - 1) / T, T>>>(ei, E, n);

    // zero accumulators + degree
    int z1 = n * (HID_C / 4);
    int z2 = n * (OUT_C / 4);
    int z3 = (n + 3) / 4;
    zero4_kernel<<<(z1 + T - 1) / T, T>>>((float4*)agg1, z1);
    zero4_kernel<<<(z2 + T - 1) / T, T>>>((float4*)agg2, z2);
    zero4_kernel<<<(z3 + T - 1) / T, T>>>((float4*)dinv, z3);

    deg_kernel<<<(E + T - 1) / T, T>>>(E);
    dinv_kernel<<<(n + T - 1) / T, T>>>(n);

    // layer 1
    sgemm_kernel<64, 64, 16, 4, 4, 128><<<(n + 63) / 64, 256>>>(x, W1, h1pre, n);
    {
        long long tt = (long long)E * (HID_C / 4);
        scatter_kernel<HID_C><<<(unsigned)((tt + T - 1) / T), T>>>(E, h1pre, agg1);
    }
    finalize1_kernel<<<(n * (HID_C / 4) + T - 1) / T, T>>>(b1, n);

    // layer 2
    sgemm_kernel<64, 32, 16, 4, 2, 64><<<(n + 63) / 64, 256>>>(agg1, W2, h2pre, n);
    {
        long long tt = (long long)E * (OUT_C / 4);
        scatter_kernel<OUT_C><<<(unsigned)((tt + T - 1) / T), T>>>(E, h2pre, agg2);
    }
    finalize2_kernel<<<(n * (OUT_C / 4) + T - 1) / T, T>>>(b2, n);

    // fused concat-linear-logsoftmax
    final_kernel<<<(n + 31) / 32, 256>>>(x, Wl, bl, out, n);
}

// round 8
// speedup vs baseline: 1.7274x; 1.7274x over previous
#include <cuda_runtime.h>
#include <cuda_bf16.h>
#include <math.h>

#define IN_C  128
#define HID_C 64
#define OUT_C 32
#define NMAX  100096   // padded headroom, n = 100000
#define EMAX  1600512
#define SCAN_BLK 1024

// ---------------- scratch (device globals; no allocation allowed) ----------
__device__ int   g_is64;
__device__ __align__(16) int   g_src [EMAX];
__device__ __align__(16) int   g_dst [EMAX];
__device__ __align__(16) int   g_esrc[EMAX];        // CSR: src sorted by dst
__device__ __align__(16) int   g_cnt   [NMAX];      // in-degree
__device__ __align__(16) int   g_rowptr[NMAX];      // exclusive scan of cnt
__device__ __align__(16) int   g_cursor[NMAX];      // fill cursors
__device__ __align__(16) int   g_bsum  [SCAN_BLK];  // block sums for scan
__device__ __align__(16) float g_dinv [NMAX];
__device__ __align__(16) float g_h1pre[NMAX * HID_C];
__device__ __align__(16) float g_agg1 [NMAX * HID_C];   // h1 after gather1
__device__ __align__(16) float g_h2pre[NMAX * OUT_C];
__device__ __align__(16) float g_agg2 [NMAX * OUT_C];   // h2 after gather2

// ---------------- dtype detect --------------------------------------------
__global__ void detect_kernel(const void* ei, int n) {
    const long long* p = (const long long*)ei;
    int ok = 1;
    for (int i = 0; i < 64; i++) {
        long long v = p[i];
        if (v < 0 || v >= (long long)n) { ok = 0; break; }
    }
    g_is64 = ok;
}

// convert indices to int32 + count in-degree
__global__ void convert_kernel(const void* ei, int E, int n) {
    int i = blockIdx.x * blockDim.x + threadIdx.x;
    if (i >= E) return;
    int s, d;
    if (g_is64) {
        const long long* p = (const long long*)ei;
        s = (int)p[i];
        d = (int)p[E + i];
    } else {
        const int* p = (const int*)ei;
        s = p[i];
        d = p[E + i];
    }
    s = (unsigned)s < (unsigned)n ? s : 0;
    d = (unsigned)d < (unsigned)n ? d : 0;
    g_src[i] = s;
    g_dst[i] = d;
    atomicAdd(&g_cnt[d], 1);
}

__global__ void zero_int_kernel(int* p, int n) {
    int i = blockIdx.x * blockDim.x + threadIdx.x;
    if (i < n) p[i] = 0;
}

// dinv from integer counts
__global__ void dinv_kernel(int n) {
    int i = blockIdx.x * blockDim.x + threadIdx.x;
    if (i < n) g_dinv[i] = rsqrtf((float)g_cnt[i] + 1.0f);
}

// ---------------- scan (exclusive) of g_cnt -> g_rowptr ---------------------
// pass 1: per-block inclusive scan; write incl values into rowptr, block sum to bsum
__global__ void scan1_kernel(int n) {
    __shared__ int sm[SCAN_BLK];
    int tid = threadIdx.x;
    int gi = blockIdx.x * SCAN_BLK + tid;
    int v = (gi < n) ? g_cnt[gi] : 0;
    sm[tid] = v;
    __syncthreads();
    for (int off = 1; off < SCAN_BLK; off <<= 1) {
        int t = (tid >= off) ? sm[tid - off] : 0;
        __syncthreads();
        sm[tid] += t;
        __syncthreads();
    }
    if (gi < n) g_rowptr[gi] = sm[tid];           // inclusive for now
    if (tid == SCAN_BLK - 1) g_bsum[blockIdx.x] = sm[tid];
}
// pass 2: single block exclusive scan of block sums
__global__ void scan2_kernel(int nblocks) {
    __shared__ int sm[SCAN_BLK];
    int tid = threadIdx.x;
    int v = (tid < nblocks) ? g_bsum[tid] : 0;
    sm[tid] = v;
    __syncthreads();
    for (int off = 1; off < SCAN_BLK; off <<= 1) {
        int t = (tid >= off) ? sm[tid - off] : 0;
        __syncthreads();
        sm[tid] += t;
        __syncthreads();
    }
    if (tid < nblocks) g_bsum[tid] = sm[tid] - v; // exclusive
}
// pass 3: rowptr[i] = incl[i] - cnt[i] + bsum[block]  (exclusive), cursor=rowptr
__global__ void scan3_kernel(int n) {
    int gi = blockIdx.x * SCAN_BLK + threadIdx.x;
    if (gi < n) {
        int r = g_rowptr[gi] - g_cnt[gi] + g_bsum[blockIdx.x];
        g_rowptr[gi] = r;
        g_cursor[gi] = r;
    }
}

// ---------------- CSR fill --------------------------------------------------
__global__ void fill_kernel(int E) {
    int e = blockIdx.x * blockDim.x + threadIdx.x;
    if (e >= E) return;
    int d = g_dst[e];
    int pos = atomicAdd(&g_cursor[d], 1);
    g_esrc[pos] = g_src[e];
}

// ---------------- tiled SGEMM: C[M,BN] = A[M,K] @ B[K,BN] -------------------
template <int BM, int BN, int BK, int TM, int TN, int K>
__global__ void sgemm_kernel(const float* __restrict__ A,
                             const float* __restrict__ B,
                             float* __restrict__ C, int M) {
    constexpr int THREADS = (BM / TM) * (BN / TN);
    __shared__ float As[BK][BM];
    __shared__ float Bs[BK][BN];

    const int tid = threadIdx.x;
    const int tx = tid % (BN / TN);
    const int ty = tid / (BN / TN);
    const int rowBase = blockIdx.x * BM;

    float acc[TM][TN];
#pragma unroll
    for (int i = 0; i < TM; i++)
#pragma unroll
        for (int j = 0; j < TN; j++) acc[i][j] = 0.f;

    for (int kt = 0; kt < K; kt += BK) {
        constexpr int A_LD4 = BM * BK / 4;
#pragma unroll
        for (int i = tid; i < A_LD4; i += THREADS) {
            int idx = i * 4;
            int r = idx / BK;
            int c = idx % BK;
            int grow = rowBase + r;
            float4 v = (grow < M) ? *(const float4*)(A + (size_t)grow * K + kt + c)
                                  : make_float4(0.f, 0.f, 0.f, 0.f);
            As[c + 0][r] = v.x; As[c + 1][r] = v.y;
            As[c + 2][r] = v.z; As[c + 3][r] = v.w;
        }
        constexpr int B_LD4 = BK * BN / 4;
#pragma unroll
        for (int i = tid; i < B_LD4; i += THREADS) {
            int idx = i * 4;
            int r = idx / BN;
            int c = idx % BN;
            *(float4*)(&Bs[r][c]) = *(const float4*)(B + (size_t)(kt + r) * BN + c);
        }
        __syncthreads();

#pragma unroll
        for (int k = 0; k < BK; k++) {
            float ra[TM], rb[TN];
#pragma unroll
            for (int i = 0; i < TM; i++) ra[i] = As[k][ty * TM + i];
#pragma unroll
            for (int j = 0; j < TN; j++) rb[j] = Bs[k][tx * TN + j];
#pragma unroll
            for (int i = 0; i < TM; i++)
#pragma unroll
                for (int j = 0; j < TN; j++) acc[i][j] += ra[i] * rb[j];
        }
        __syncthreads();
    }

#pragma unroll
    for (int i = 0; i < TM; i++) {
        int grow = rowBase + ty * TM + i;
        if (grow < M) {
#pragma unroll
            for (int j = 0; j < TN; j++)
                C[(size_t)grow * BN + tx * TN + j] = acc[i][j];
        }
    }
}

// ---------------- CSR gather aggregation (fused finalize) -------------------
// layer 1: C=64, warp per node, lane owns channels {lane, lane+32}; relu+bias
__global__ void gather1_kernel(const float* __restrict__ b1, int n) {
    int warp = threadIdx.x >> 5;
    int lane = threadIdx.x & 31;
    int node = blockIdx.x * 8 + warp;
    if (node >= n) return;

    int start = g_rowptr[node];
    int cnt   = g_cnt[node];
    float dd  = g_dinv[node];

    float a0 = 0.f, a1 = 0.f;
    const float* __restrict__ h = g_h1pre;
    for (int i = 0; i < cnt; i++) {
        int s = g_esrc[start + i];
        float nm = g_dinv[s] * dd;
        const float* row = h + (size_t)s * HID_C;
        a0 += row[lane]      * nm;
        a1 += row[lane + 32] * nm;
    }
    float d2 = dd * dd;
    const float* hn = h + (size_t)node * HID_C;
    float o0 = fmaxf(a0 + hn[lane]      * d2 + b1[lane],      0.f);
    float o1 = fmaxf(a1 + hn[lane + 32] * d2 + b1[lane + 32], 0.f);
    float* on = g_agg1 + (size_t)node * HID_C;
    on[lane]      = o0;
    on[lane + 32] = o1;
}

// layer 2: C=32, warp per node, lane owns 1 channel; bias only
__global__ void gather2_kernel(const float* __restrict__ b2, int n) {
    int warp = threadIdx.x >> 5;
    int lane = threadIdx.x & 31;
    int node = blockIdx.x * 8 + warp;
    if (node >= n) return;

    int start = g_rowptr[node];
    int cnt   = g_cnt[node];
    float dd  = g_dinv[node];

    float a0 = 0.f;
    const float* __restrict__ h = g_h2pre;
    for (int i = 0; i < cnt; i++) {
        int s = g_esrc[start + i];
        float nm = g_dinv[s] * dd;
        a0 += h[(size_t)s * OUT_C + lane] * nm;
    }
    float d2 = dd * dd;
    g_agg2[(size_t)node * OUT_C + lane] =
        a0 + g_h2pre[(size_t)node * OUT_C + lane] * d2 + b2[lane];
}

// ---------------- fused final layer: [x,h1,h2] @ Wl + bl -> log_softmax -----
__global__ void final_kernel(const float* __restrict__ x,
                             const float* __restrict__ Wl,
                             const float* __restrict__ bl,
                             float* __restrict__ out, int n) {
    constexpr int KTOT = IN_C + HID_C + OUT_C;   // 224
    __shared__ float Ws[KTOT * OUT_C];           // 28 KB
    const int tid = threadIdx.x;
    for (int i = tid; i < KTOT * OUT_C / 4; i += blockDim.x)
        ((float4*)Ws)[i] = ((const float4*)Wl)[i];
    __syncthreads();

    const int warp = tid >> 5;
    const int lane = tid & 31;
    const int rowBase = (blockIdx.x * 8 + warp) * 4;
    if (rowBase >= n) return;

    float fr[4][7];
#pragma unroll
    for (int r = 0; r < 4; r++) {
        int row = rowBase + r;
        if (row < n) {
#pragma unroll
            for (int i = 0; i < 4; i++)
                fr[r][i] = x[(size_t)row * IN_C + i * 32 + lane];
            fr[r][4] = g_agg1[(size_t)row * HID_C + lane];
            fr[r][5] = g_agg1[(size_t)row * HID_C + 32 + lane];
            fr[r][6] = g_agg2[(size_t)row * OUT_C + lane];
        } else {
#pragma unroll
            for (int i = 0; i < 7; i++) fr[r][i] = 0.f;
        }
    }

    float acc[4] = {0.f, 0.f, 0.f, 0.f};
#pragma unroll
    for (int seg = 0; seg < 7; seg++) {
#pragma unroll
        for (int kk = 0; kk < 32; kk++) {
            float w = Ws[(seg * 32 + kk) * OUT_C + lane];
            acc[0] += __shfl_sync(0xffffffffu, fr[0][seg], kk) * w;
            acc[1] += __shfl_sync(0xffffffffu, fr[1][seg], kk) * w;
            acc[2] += __shfl_sync(0xffffffffu, fr[2][seg], kk) * w;
            acc[3] += __shfl_sync(0xffffffffu, fr[3][seg], kk) * w;
        }
    }

    float blv = bl[lane];
#pragma unroll
    for (int r = 0; r < 4; r++) {
        int row = rowBase + r;
        if (row >= n) break;
        float lg = acc[r] + blv;
        float m = lg;
#pragma unroll
        for (int o = 16; o > 0; o >>= 1)
            m = fmaxf(m, __shfl_xor_sync(0xffffffffu, m, o));
        float ex = __expf(lg - m);
        float s = ex;
#pragma unroll
        for (int o = 16; o > 0; o >>= 1)
            s += __shfl_xor_sync(0xffffffffu, s, o);
        out[(size_t)row * OUT_C + lane] = lg - m - __logf(s);
    }
}

// ---------------- launch ----------------------------------------------------
extern "C" void kernel_launch(void* const* d_in, const int* in_sizes, int n_in,
                              void* d_out, int out_size) {
    const float* x  = (const float*)d_in[0];
    const void*  ei = d_in[1];
    const float* W1 = (const float*)d_in[2];
    const float* b1 = (const float*)d_in[3];
    const float* W2 = (const float*)d_in[4];
    const float* b2 = (const float*)d_in[5];
    const float* Wl = (const float*)d_in[6];
    const float* bl = (const float*)d_in[7];
    float* out = (float*)d_out;

    const int n = in_sizes[0] / IN_C;
    const int E = in_sizes[1] / 2;

    int* cnt;
    float *h1pre, *agg1, *h2pre;
    cudaGetSymbolAddress((void**)&cnt,   g_cnt);
    cudaGetSymbolAddress((void**)&h1pre, g_h1pre);
    cudaGetSymbolAddress((void**)&agg1,  g_agg1);
    cudaGetSymbolAddress((void**)&h2pre, g_h2pre);

    const int T = 256;
    const int nScanBlocks = (n + SCAN_BLK - 1) / SCAN_BLK;

    // ---- graph preprocessing: detect dtype, convert+count, scan, fill, dinv
    detect_kernel<<<1, 1>>>(ei, n);
    zero_int_kernel<<<(n + T - 1) / T, T>>>(cnt, n);
    convert_kernel<<<(E + T - 1) / T, T>>>(ei, E, n);
    dinv_kernel<<<(n + T - 1) / T, T>>>(n);
    scan1_kernel<<<nScanBlocks, SCAN_BLK>>>(n);
    scan2_kernel<<<1, SCAN_BLK>>>(nScanBlocks);
    scan3_kernel<<<nScanBlocks, SCAN_BLK>>>(n);
    fill_kernel<<<(E + T - 1) / T, T>>>(E);

    // ---- layer 1: GEMM then CSR gather (fused self-loop+bias+relu)
    sgemm_kernel<64, 64, 16, 4, 4, 128><<<(n + 63) / 64, 256>>>(x, W1, h1pre, n);
    gather1_kernel<<<(n + 7) / 8, 256>>>(b1, n);

    // ---- layer 2
    sgemm_kernel<64, 32, 16, 4, 2, 64><<<(n + 63) / 64, 256>>>(agg1, W2, h2pre, n);
    gather2_kernel<<<(n + 7) / 8, 256>>>(b2, n);

    // ---- fused concat-linear-logsoftmax
    final_kernel<<<(n + 31) / 32, 256>>>(x, Wl, bl, out, n);
}

// round 13
// speedup vs baseline: 1.8616x; 1.0777x over previous
#include <cuda_runtime.h>
#include <cuda_bf16.h>
#include <math.h>

#define IN_C  128
#define HID_C 64
#define OUT_C 32
#define NMAX  100096
#define EMAX  1600512
#define SCAN_BLK 1024

// ---------------- scratch (device globals) ----------------------------------
__device__ int   g_is64;
__device__ __align__(16) int   g_esrc  [EMAX];      // CSR: src sorted by dst
__device__ __align__(16) int   g_cnt   [NMAX];      // in-degree
__device__ __align__(16) int   g_rowptr[NMAX];      // exclusive scan of cnt
__device__ __align__(16) int   g_cursor[NMAX];
__device__ __align__(16) int   g_bsum  [SCAN_BLK];
__device__ __align__(16) float g_dinv  [NMAX];
__device__ __align__(16) float g_h1pre [NMAX * HID_C];
__device__ __align__(16) float g_agg1  [NMAX * HID_C];
__device__ __align__(16) float g_h2pre [NMAX * OUT_C];
__device__ __align__(16) float g_agg2  [NMAX * OUT_C];

// ---------------- dtype detect ----------------------------------------------
__global__ void detect_kernel(const void* ei, int n) {
    const long long* p = (const long long*)ei;
    int ok = 1;
#pragma unroll
    for (int i = 0; i < 16; i++) {
        long long v = p[i];
        if (v < 0 || v >= (long long)n) ok = 0;
    }
    g_is64 = ok;
}

// pass 1: count in-degree (reads ei directly)
__global__ void count_kernel(const void* ei, int E, int n) {
    int i = blockIdx.x * blockDim.x + threadIdx.x;
    if (i >= E) return;
    int d;
    if (g_is64) d = (int)((const long long*)ei)[E + i];
    else        d = ((const int*)ei)[E + i];
    d = (unsigned)d < (unsigned)n ? d : 0;
    atomicAdd(&g_cnt[d], 1);
}

__global__ void dinv_kernel(int n) {
    int i = blockIdx.x * blockDim.x + threadIdx.x;
    if (i < n) g_dinv[i] = rsqrtf((float)g_cnt[i] + 1.0f);
}

// ---------------- scan (exclusive) of g_cnt -> g_rowptr ---------------------
__global__ void scan1_kernel(int n) {
    __shared__ int sm[SCAN_BLK];
    int tid = threadIdx.x;
    int gi = blockIdx.x * SCAN_BLK + tid;
    int v = (gi < n) ? g_cnt[gi] : 0;
    sm[tid] = v;
    __syncthreads();
    for (int off = 1; off < SCAN_BLK; off <<= 1) {
        int t = (tid >= off) ? sm[tid - off] : 0;
        __syncthreads();
        sm[tid] += t;
        __syncthreads();
    }
    if (gi < n) g_rowptr[gi] = sm[tid];
    if (tid == SCAN_BLK - 1) g_bsum[blockIdx.x] = sm[tid];
}
__global__ void scan2_kernel(int nblocks) {
    __shared__ int sm[SCAN_BLK];
    int tid = threadIdx.x;
    int v = (tid < nblocks) ? g_bsum[tid] : 0;
    sm[tid] = v;
    __syncthreads();
    for (int off = 1; off < SCAN_BLK; off <<= 1) {
        int t = (tid >= off) ? sm[tid - off] : 0;
        __syncthreads();
        sm[tid] += t;
        __syncthreads();
    }
    if (tid < nblocks) g_bsum[tid] = sm[tid] - v;
}
__global__ void scan3_kernel(int n) {
    int gi = blockIdx.x * SCAN_BLK + threadIdx.x;
    if (gi < n) {
        int r = g_rowptr[gi] - g_cnt[gi] + g_bsum[blockIdx.x];
        g_rowptr[gi] = r;
        g_cursor[gi] = r;
    }
}

// pass 2: fill CSR (reads ei directly)
__global__ void fill_kernel(const void* ei, int E, int n) {
    int e = blockIdx.x * blockDim.x + threadIdx.x;
    if (e >= E) return;
    int s, d;
    if (g_is64) {
        const long long* p = (const long long*)ei;
        s = (int)p[e];
        d = (int)p[E + e];
    } else {
        const int* p = (const int*)ei;
        s = p[e];
        d = p[E + e];
    }
    s = (unsigned)s < (unsigned)n ? s : 0;
    d = (unsigned)d < (unsigned)n ? d : 0;
    int pos = atomicAdd(&g_cursor[d], 1);
    g_esrc[pos] = s;
}

// ---------------- tiled SGEMM: C[M,BN] = A[M,K] @ B[K,BN] -------------------
// 256 threads, microtile TM x TN, float4 smem reads.
template <int BM, int BN, int BK, int TM, int TN, int K>
__global__ void sgemm_kernel(const float* __restrict__ A,
                             const float* __restrict__ B,
                             float* __restrict__ C, int M) {
    constexpr int THREADS = (BM / TM) * (BN / TN);
    __shared__ float As[BK][BM];
    __shared__ float Bs[BK][BN];

    const int tid = threadIdx.x;
    const int tx = tid % (BN / TN);
    const int ty = tid / (BN / TN);
    const int rowBase = blockIdx.x * BM;

    float acc[TM][TN];
#pragma unroll
    for (int i = 0; i < TM; i++)
#pragma unroll
        for (int j = 0; j < TN; j++) acc[i][j] = 0.f;

    for (int kt = 0; kt < K; kt += BK) {
        constexpr int A_LD4 = BM * BK / 4;
#pragma unroll
        for (int i = tid; i < A_LD4; i += THREADS) {
            int idx = i * 4;
            int r = idx / BK;
            int c = idx % BK;
            int grow = rowBase + r;
            float4 v = (grow < M) ? *(const float4*)(A + (size_t)grow * K + kt + c)
                                  : make_float4(0.f, 0.f, 0.f, 0.f);
            As[c + 0][r] = v.x; As[c + 1][r] = v.y;
            As[c + 2][r] = v.z; As[c + 3][r] = v.w;
        }
        constexpr int B_LD4 = BK * BN / 4;
#pragma unroll
        for (int i = tid; i < B_LD4; i += THREADS) {
            int idx = i * 4;
            int r = idx / BN;
            int c = idx % BN;
            *(float4*)(&Bs[r][c]) = *(const float4*)(B + (size_t)(kt + r) * BN + c);
        }
        __syncthreads();

#pragma unroll
        for (int k = 0; k < BK; k++) {
            float ra[TM], rb[TN];
#pragma unroll
            for (int i = 0; i < TM; i += 4)
                *(float4*)&ra[i] = *(const float4*)&As[k][ty * TM + i];
#pragma unroll
            for (int j = 0; j < TN; j += 2) {
                if (TN >= 4 && (j & 3) == 0 && j + 4 <= TN)
                    ;  // handled below
            }
            if (TN == 4)      *(float4*)&rb[0] = *(const float4*)&Bs[k][tx * TN];
            else if (TN == 2) *(float2*)&rb[0] = *(const float2*)&Bs[k][tx * TN];
#pragma unroll
            for (int i = 0; i < TM; i++)
#pragma unroll
                for (int j = 0; j < TN; j++) acc[i][j] += ra[i] * rb[j];
        }
        __syncthreads();
    }

#pragma unroll
    for (int i = 0; i < TM; i++) {
        int grow = rowBase + ty * TM + i;
        if (grow < M) {
            if (TN == 4)
                *(float4*)(C + (size_t)grow * BN + tx * TN) = *(float4*)&acc[i][0];
            else if (TN == 2)
                *(float2*)(C + (size_t)grow * BN + tx * TN) = *(float2*)&acc[i][0];
        }
    }
}

// ---------------- CSR gather aggregation (fused finalize) -------------------
// layer 1: warp per node, lane owns channels {2*lane, 2*lane+1} (float2)
__global__ void gather1_kernel(const float* __restrict__ b1, int n) {
    int warp = threadIdx.x >> 5;
    int lane = threadIdx.x & 31;
    int node = blockIdx.x * 8 + warp;
    if (node >= n) return;

    int start = g_rowptr[node];
    int cnt   = g_cnt[node];
    float dd  = g_dinv[node];

    const float2* __restrict__ h = (const float2*)g_h1pre;   // 32 float2/row
    float ax = 0.f, ay = 0.f;
    int i = 0;
    for (; i + 2 <= cnt; i += 2) {
        int s0 = g_esrc[start + i];
        int s1 = g_esrc[start + i + 1];
        float nm0 = g_dinv[s0] * dd;
        float nm1 = g_dinv[s1] * dd;
        float2 v0 = h[(size_t)s0 * 32 + lane];
        float2 v1 = h[(size_t)s1 * 32 + lane];
        ax += v0.x * nm0 + v1.x * nm1;
        ay += v0.y * nm0 + v1.y * nm1;
    }
    if (i < cnt) {
        int s0 = g_esrc[start + i];
        float nm0 = g_dinv[s0] * dd;
        float2 v0 = h[(size_t)s0 * 32 + lane];
        ax += v0.x * nm0;
        ay += v0.y * nm0;
    }
    float d2 = dd * dd;
    float2 hn = h[(size_t)node * 32 + lane];
    float2 bb = ((const float2*)b1)[lane];
    float2 o;
    o.x = fmaxf(ax + hn.x * d2 + bb.x, 0.f);
    o.y = fmaxf(ay + hn.y * d2 + bb.y, 0.f);
    ((float2*)g_agg1)[(size_t)node * 32 + lane] = o;
}

// layer 2: warp per node, lane owns 1 channel
__global__ void gather2_kernel(const float* __restrict__ b2, int n) {
    int warp = threadIdx.x >> 5;
    int lane = threadIdx.x & 31;
    int node = blockIdx.x * 8 + warp;
    if (node >= n) return;

    int start = g_rowptr[node];
    int cnt   = g_cnt[node];
    float dd  = g_dinv[node];

    const float* __restrict__ h = g_h2pre;
    float a0 = 0.f;
    int i = 0;
    for (; i + 2 <= cnt; i += 2) {
        int s0 = g_esrc[start + i];
        int s1 = g_esrc[start + i + 1];
        float nm0 = g_dinv[s0] * dd;
        float nm1 = g_dinv[s1] * dd;
        a0 += h[(size_t)s0 * OUT_C + lane] * nm0
            + h[(size_t)s1 * OUT_C + lane] * nm1;
    }
    if (i < cnt) {
        int s0 = g_esrc[start + i];
        a0 += h[(size_t)s0 * OUT_C + lane] * (g_dinv[s0] * dd);
    }
    float d2 = dd * dd;
    g_agg2[(size_t)node * OUT_C + lane] =
        a0 + h[(size_t)node * OUT_C + lane] * d2 + b2[lane];
}

// ---------------- fused final layer: [x,h1,h2] @ Wl + bl -> log_softmax -----
__global__ void final_kernel(const float* __restrict__ x,
                             const float* __restrict__ Wl,
                             const float* __restrict__ bl,
                             float* __restrict__ out, int n) {
    constexpr int KTOT = IN_C + HID_C + OUT_C;   // 224
    __shared__ float Ws[KTOT * OUT_C];           // 28 KB
    const int tid = threadIdx.x;
    for (int i = tid; i < KTOT * OUT_C / 4; i += blockDim.x)
        ((float4*)Ws)[i] = ((const float4*)Wl)[i];
    __syncthreads();

    const int warp = tid >> 5;
    const int lane = tid & 31;
    const int rowBase = (blockIdx.x * 8 + warp) * 4;
    if (rowBase >= n) return;

    float fr[4][7];
#pragma unroll
    for (int r = 0; r < 4; r++) {
        int row = rowBase + r;
        if (row < n) {
#pragma unroll
            for (int i = 0; i < 4; i++)
                fr[r][i] = x[(size_t)row * IN_C + i * 32 + lane];
            fr[r][4] = g_agg1[(size_t)row * HID_C + lane];
            fr[r][5] = g_agg1[(size_t)row * HID_C + 32 + lane];
            fr[r][6] = g_agg2[(size_t)row * OUT_C + lane];
        } else {
#pragma unroll
            for (int i = 0; i < 7; i++) fr[r][i] = 0.f;
        }
    }

    float acc[4] = {0.f, 0.f, 0.f, 0.f};
#pragma unroll
    for (int seg = 0; seg < 7; seg++) {
#pragma unroll
        for (int kk = 0; kk < 32; kk++) {
            float w = Ws[(seg * 32 + kk) * OUT_C + lane];
            acc[0] += __shfl_sync(0xffffffffu, fr[0][seg], kk) * w;
            acc[1] += __shfl_sync(0xffffffffu, fr[1][seg], kk) * w;
            acc[2] += __shfl_sync(0xffffffffu, fr[2][seg], kk) * w;
            acc[3] += __shfl_sync(0xffffffffu, fr[3][seg], kk) * w;
        }
    }

    float blv = bl[lane];
#pragma unroll
    for (int r = 0; r < 4; r++) {
        int row = rowBase + r;
        if (row >= n) break;
        float lg = acc[r] + blv;
        float m = lg;
#pragma unroll
        for (int o = 16; o > 0; o >>= 1)
            m = fmaxf(m, __shfl_xor_sync(0xffffffffu, m, o));
        float ex = __expf(lg - m);
        float s = ex;
#pragma unroll
        for (int o = 16; o > 0; o >>= 1)
            s += __shfl_xor_sync(0xffffffffu, s, o);
        out[(size_t)row * OUT_C + lane] = lg - m - __logf(s);
    }
}

// ---------------- launch ----------------------------------------------------
extern "C" void kernel_launch(void* const* d_in, const int* in_sizes, int n_in,
                              void* d_out, int out_size) {
    const float* x  = (const float*)d_in[0];
    const void*  ei = d_in[1];
    const float* W1 = (const float*)d_in[2];
    const float* b1 = (const float*)d_in[3];
    const float* W2 = (const float*)d_in[4];
    const float* b2 = (const float*)d_in[5];
    const float* Wl = (const float*)d_in[6];
    const float* bl = (const float*)d_in[7];
    float* out = (float*)d_out;

    const int n = in_sizes[0] / IN_C;
    const int E = in_sizes[1] / 2;

    int* cnt;
    float *h1pre, *agg1, *h2pre;
    cudaGetSymbolAddress((void**)&cnt,   g_cnt);
    cudaGetSymbolAddress((void**)&h1pre, g_h1pre);
    cudaGetSymbolAddress((void**)&agg1,  g_agg1);
    cudaGetSymbolAddress((void**)&h2pre, g_h2pre);

    // Lazy side-stream/events: created on the first (uncaptured correctness)
    // call; re-used on the capture call. Same work every call.
    static cudaStream_t s2 = nullptr;
    static cudaEvent_t evFork = nullptr, evJoin = nullptr;
    if (s2 == nullptr) {
        cudaStreamCreateWithFlags(&s2, cudaStreamNonBlocking);
        cudaEventCreateWithFlags(&evFork, cudaEventDisableTiming);
        cudaEventCreateWithFlags(&evJoin, cudaEventDisableTiming);
    }

    const int T = 256;
    const int nScanBlocks = (n + SCAN_BLK - 1) / SCAN_BLK;

    // ---- fork: CSR preprocessing on s2, concurrent with sgemm1 on stream 0
    cudaEventRecord(evFork, 0);
    cudaStreamWaitEvent(s2, evFork, 0);

    detect_kernel<<<1, 1, 0, s2>>>(ei, n);
    cudaMemsetAsync(cnt, 0, (size_t)n * sizeof(int), s2);
    count_kernel<<<(E + T - 1) / T, T, 0, s2>>>(ei, E, n);
    dinv_kernel<<<(n + T - 1) / T, T, 0, s2>>>(n);
    scan1_kernel<<<nScanBlocks, SCAN_BLK, 0, s2>>>(n);
    scan2_kernel<<<1, SCAN_BLK, 0, s2>>>(nScanBlocks);
    scan3_kernel<<<nScanBlocks, SCAN_BLK, 0, s2>>>(n);
    fill_kernel<<<(E + T - 1) / T, T, 0, s2>>>(ei, E, n);

    // main stream: layer-1 GEMM (independent of CSR)
    sgemm_kernel<128, 64, 16, 8, 4, 128><<<(n + 127) / 128, 256>>>(x, W1, h1pre, n);

    // ---- join
    cudaEventRecord(evJoin, s2);
    cudaStreamWaitEvent(0, evJoin, 0);

    // layer 1 gather (fused self-loop + bias + relu)
    gather1_kernel<<<(n + 7) / 8, 256>>>(b1, n);

    // layer 2
    sgemm_kernel<128, 32, 16, 8, 2, 64><<<(n + 127) / 128, 256>>>(agg1, W2, h2pre, n);
    gather2_kernel<<<(n + 7) / 8, 256>>>(b2, n);

    // fused concat-linear-logsoftmax
    final_kernel<<<(n + 31) / 32, 256>>>(x, Wl, bl, out, n);
}